// round 1
// baseline (speedup 1.0000x reference)
#include <cuda_runtime.h>
#include <cuda_bf16.h>
#include <cstdint>

// Problem constants
#define B_ 32
#define L_ 4096
#define H_ 128
#define V_ 32000
#define TOK_ 131072            // B_*L_
#define LN_EPS 1e-5f
#define NORM_EPS 1e-12f

// -------- scratch (device globals; no allocation allowed) --------
__device__ float g_z1[(size_t)TOK_ * 256];   // relu(h@W1+b1)      128 MB
__device__ float g_kn[(size_t)TOK_ * 128];   // normalized k        64 MB
__device__ float g_nrm[TOK_];                // ||k|| clamped      512 KB
__device__ float g_M[(size_t)B_ * 128 * 128];// final scan state     2 MB
__device__ float g_r2[B_ * 128];             // read@Wrp+brp        16 KB

// ============================================================================
// K1: z1 = relu(embed[seq] @ W1 + b1)     (W1 in smem, 8 tokens per pass)
// ============================================================================
__global__ __launch_bounds__(256) void k_ffn1(
    const int* __restrict__ seq, const float* __restrict__ embed,
    const float* __restrict__ W1, const float* __restrict__ b1)
{
    extern __shared__ float sm[];
    float* W1s = sm;            // 128*256
    float* hs  = sm + 32768;    // [i][tok] 128*8
    const int j = threadIdx.x;  // output column 0..255
    for (int i = j; i < 128 * 256; i += 256) W1s[i] = W1[i];
    const float bj = b1[j];
    __syncthreads();

    const int nIter = TOK_ / 8;
    for (int it = blockIdx.x; it < nIter; it += gridDim.x) {
        const int t0 = it * 8;
        __syncthreads();   // protect hs from previous pass readers
        for (int e = j; e < 1024; e += 256) {
            const int tok = e >> 7, i = e & 127;
            hs[i * 8 + tok] = embed[(size_t)seq[t0 + tok] * 128 + i];
        }
        __syncthreads();
        float acc[8];
#pragma unroll
        for (int k = 0; k < 8; k++) acc[k] = bj;
#pragma unroll 8
        for (int i = 0; i < 128; i++) {
            const float w = W1s[i * 256 + j];
            const float4 ha = *(const float4*)(hs + i * 8);
            const float4 hb = *(const float4*)(hs + i * 8 + 4);
            acc[0] = fmaf(ha.x, w, acc[0]);
            acc[1] = fmaf(ha.y, w, acc[1]);
            acc[2] = fmaf(ha.z, w, acc[2]);
            acc[3] = fmaf(ha.w, w, acc[3]);
            acc[4] = fmaf(hb.x, w, acc[4]);
            acc[5] = fmaf(hb.y, w, acc[5]);
            acc[6] = fmaf(hb.z, w, acc[6]);
            acc[7] = fmaf(hb.w, w, acc[7]);
        }
#pragma unroll
        for (int k = 0; k < 8; k++)
            g_z1[(size_t)(t0 + k) * 256 + j] = fmaxf(acc[k], 0.0f);
    }
}

// ============================================================================
// K2: y = z1@W2+b2; x = h+y; h2 = LN(x); k = h2@Wkp; store kn, ||k||
// ============================================================================
__device__ __forceinline__ void reduceSum8(float* v, float* red, int tid)
{
#pragma unroll
    for (int k = 0; k < 8; k++) {
        v[k] += __shfl_xor_sync(0xffffffffu, v[k], 16);
        v[k] += __shfl_xor_sync(0xffffffffu, v[k], 8);
        v[k] += __shfl_xor_sync(0xffffffffu, v[k], 4);
        v[k] += __shfl_xor_sync(0xffffffffu, v[k], 2);
        v[k] += __shfl_xor_sync(0xffffffffu, v[k], 1);
    }
    const int w = tid >> 5;
    __syncthreads();                 // red buffer free
    if ((tid & 31) == 0) {
#pragma unroll
        for (int k = 0; k < 8; k++) red[w * 8 + k] = v[k];
    }
    __syncthreads();
#pragma unroll
    for (int k = 0; k < 8; k++)
        v[k] = (red[k] + red[8 + k]) + (red[16 + k] + red[24 + k]);
}

__global__ __launch_bounds__(128) void k_ffn2(
    const int* __restrict__ seq, const float* __restrict__ embed,
    const float* __restrict__ W2, const float* __restrict__ b2,
    const float* __restrict__ ln_g, const float* __restrict__ ln_b,
    const float* __restrict__ Wkp)
{
    extern __shared__ float sm[];
    float* W2s  = sm;               // 256*128
    float* Wkps = sm + 32768;       // 128*128
    float* z1s  = sm + 49152;       // [i][tok] 256*8
    float* h2s  = sm + 51200;       // [i][tok] 128*8
    float* red  = sm + 52224;       // 4*8
    const int j = threadIdx.x;      // 0..127
    for (int i = j; i < 32768; i += 128) W2s[i]  = W2[i];
    for (int i = j; i < 16384; i += 128) Wkps[i] = Wkp[i];
    const float b2j = b2[j], gj = ln_g[j], bbj = ln_b[j];
    __syncthreads();

    const int nIter = TOK_ / 8;
    for (int it = blockIdx.x; it < nIter; it += gridDim.x) {
        const int t0 = it * 8;
        __syncthreads();
        for (int e = j; e < 2048; e += 128) {
            const int tok = e >> 8, i = e & 255;
            z1s[i * 8 + tok] = g_z1[(size_t)(t0 + tok) * 256 + i];
        }
        __syncthreads();

        float y[8];
#pragma unroll
        for (int k = 0; k < 8; k++) y[k] = b2j;
#pragma unroll 8
        for (int i = 0; i < 256; i++) {
            const float w = W2s[i * 128 + j];
            const float4 a = *(const float4*)(z1s + i * 8);
            const float4 c = *(const float4*)(z1s + i * 8 + 4);
            y[0] = fmaf(a.x, w, y[0]); y[1] = fmaf(a.y, w, y[1]);
            y[2] = fmaf(a.z, w, y[2]); y[3] = fmaf(a.w, w, y[3]);
            y[4] = fmaf(c.x, w, y[4]); y[5] = fmaf(c.y, w, y[5]);
            y[6] = fmaf(c.z, w, y[6]); y[7] = fmaf(c.w, w, y[7]);
        }
        float x[8];
#pragma unroll
        for (int k = 0; k < 8; k++)
            x[k] = y[k] + embed[(size_t)seq[t0 + k] * 128 + j];

        float s[8];
#pragma unroll
        for (int k = 0; k < 8; k++) s[k] = x[k];
        reduceSum8(s, red, j);
        float mu[8];
#pragma unroll
        for (int k = 0; k < 8; k++) mu[k] = s[k] * (1.0f / 128.0f);
        float vv[8];
#pragma unroll
        for (int k = 0; k < 8; k++) { const float d = x[k] - mu[k]; vv[k] = d * d; }
        reduceSum8(vv, red, j);
        float h2[8];
#pragma unroll
        for (int k = 0; k < 8; k++)
            h2[k] = (x[k] - mu[k]) * rsqrtf(vv[k] * (1.0f / 128.0f) + LN_EPS) * gj + bbj;
#pragma unroll
        for (int k = 0; k < 8; k++) h2s[j * 8 + k] = h2[k];
        __syncthreads();

        float kk[8];
#pragma unroll
        for (int k = 0; k < 8; k++) kk[k] = 0.0f;
#pragma unroll 8
        for (int i = 0; i < 128; i++) {
            const float w = Wkps[i * 128 + j];
            const float4 a = *(const float4*)(h2s + i * 8);
            const float4 c = *(const float4*)(h2s + i * 8 + 4);
            kk[0] = fmaf(a.x, w, kk[0]); kk[1] = fmaf(a.y, w, kk[1]);
            kk[2] = fmaf(a.z, w, kk[2]); kk[3] = fmaf(a.w, w, kk[3]);
            kk[4] = fmaf(c.x, w, kk[4]); kk[5] = fmaf(c.y, w, kk[5]);
            kk[6] = fmaf(c.z, w, kk[6]); kk[7] = fmaf(c.w, w, kk[7]);
        }
        float sq[8];
#pragma unroll
        for (int k = 0; k < 8; k++) sq[k] = kk[k] * kk[k];
        reduceSum8(sq, red, j);
#pragma unroll
        for (int k = 0; k < 8; k++) {
            const float nr = fmaxf(sqrtf(sq[k]), NORM_EPS);
            g_kn[(size_t)(t0 + k) * 128 + j] = kk[k] / nr;
        }
        if (j < 8) g_nrm[t0 + j] = fmaxf(sqrtf(sq[j]), NORM_EPS);
    }
}

// ============================================================================
// K3: delta-rule scan. Rows of M are independent given kn_t. 128 CTAs
// (= 32 batches x 4 row-splits). Per-warp cp.async ring: no block barriers.
// Thread layout: warp w owns rows s*32 + w*4 + rr (rr = lane>>3),
// lane's cg = lane&7 owns cols [cg*16, cg*16+16).
// Stage layout (bytes): 8 chunks of 64B at stride 80B (conflict-free), norm @640.
// ============================================================================
#define SCAN_D 8
#define STG_F 164              // floats per stage (656 B)

__global__ __launch_bounds__(256) void k_scan()
{
    __shared__ __align__(16) float buf[8][STG_F * SCAN_D];
    const int tid  = threadIdx.x;
    const int w    = tid >> 5, lane = tid & 31;
    const int cg   = lane & 7, rr = lane >> 3;
    const int b    = blockIdx.x >> 2, s = blockIdx.x & 3;
    const int r    = s * 32 + w * 4 + rr;           // global row 0..127
    const float* __restrict__ knb  = g_kn + (size_t)b * L_ * 128;
    const float* __restrict__ nrmb = g_nrm + (size_t)b * L_;
    float* wb = &buf[w][0];
    const uint32_t wbb = (uint32_t)__cvta_generic_to_shared(wb);
    const int NSTEP = L_ - 1;

    // prologue: stages 0..6
    for (int t = 0; t < SCAN_D - 1; t++) {
        const uint32_t dst = wbb + t * 656 + (lane >> 2) * 80 + (lane & 3) * 16;
        const float* src = knb + (size_t)t * 128 + lane * 4;
        asm volatile("cp.async.cg.shared.global [%0], [%1], 16;\n" :: "r"(dst), "l"(src) : "memory");
        if (lane == 0) {
            const uint32_t dn = wbb + t * 656 + 640;
            asm volatile("cp.async.ca.shared.global [%0], [%1], 4;\n" :: "r"(dn), "l"(nrmb + t) : "memory");
        }
        asm volatile("cp.async.commit_group;\n" ::: "memory");
    }

    float m[16];
#pragma unroll
    for (int c = 0; c < 16; c++) m[c] = 0.0f;
    const int kroff = (r >> 4) * 20 + (r & 15);     // kn[r] float offset in stage

    for (int t = 0; t < NSTEP; t++) {
        asm volatile("cp.async.wait_group 6;\n" ::: "memory");
        __syncwarp();
        {   // refill slot (t-1)&7 with stage t+7
            const int ti = t + SCAN_D - 1;
            if (ti < NSTEP) {
                const int slot = ti & 7;
                const uint32_t dst = wbb + slot * 656 + (lane >> 2) * 80 + (lane & 3) * 16;
                const float* src = knb + (size_t)ti * 128 + lane * 4;
                asm volatile("cp.async.cg.shared.global [%0], [%1], 16;\n" :: "r"(dst), "l"(src) : "memory");
                if (lane == 0) {
                    const uint32_t dn = wbb + slot * 656 + 640;
                    asm volatile("cp.async.ca.shared.global [%0], [%1], 4;\n" :: "r"(dn), "l"(nrmb + ti) : "memory");
                }
            }
            asm volatile("cp.async.commit_group;\n" ::: "memory");
        }
        const float* st = wb + (t & 7) * STG_F;
        const float4 ka = *(const float4*)(st + cg * 20);
        const float4 kb = *(const float4*)(st + cg * 20 + 4);
        const float4 kc = *(const float4*)(st + cg * 20 + 8);
        const float4 kd = *(const float4*)(st + cg * 20 + 12);
        const float nrm = st[160];
        const float kr  = st[kroff] * nrm;          // raw k[r]

        float p0 = fmaf(m[0],  ka.x, fmaf(m[1],  ka.y, fmaf(m[2],  ka.z, m[3]  * ka.w)));
        float p1 = fmaf(m[4],  kb.x, fmaf(m[5],  kb.y, fmaf(m[6],  kb.z, m[7]  * kb.w)));
        float p2 = fmaf(m[8],  kc.x, fmaf(m[9],  kc.y, fmaf(m[10], kc.z, m[11] * kc.w)));
        float p3 = fmaf(m[12], kd.x, fmaf(m[13], kd.y, fmaf(m[14], kd.z, m[15] * kd.w)));
        float dot = (p0 + p1) + (p2 + p3);
        dot += __shfl_xor_sync(0xffffffffu, dot, 1);
        dot += __shfl_xor_sync(0xffffffffu, dot, 2);
        dot += __shfl_xor_sync(0xffffffffu, dot, 4);
        const float delta = kr - dot;
        m[0]  = fmaf(delta, ka.x, m[0]);  m[1]  = fmaf(delta, ka.y, m[1]);
        m[2]  = fmaf(delta, ka.z, m[2]);  m[3]  = fmaf(delta, ka.w, m[3]);
        m[4]  = fmaf(delta, kb.x, m[4]);  m[5]  = fmaf(delta, kb.y, m[5]);
        m[6]  = fmaf(delta, kb.z, m[6]);  m[7]  = fmaf(delta, kb.w, m[7]);
        m[8]  = fmaf(delta, kc.x, m[8]);  m[9]  = fmaf(delta, kc.y, m[9]);
        m[10] = fmaf(delta, kc.z, m[10]); m[11] = fmaf(delta, kc.w, m[11]);
        m[12] = fmaf(delta, kd.x, m[12]); m[13] = fmaf(delta, kd.y, m[13]);
        m[14] = fmaf(delta, kd.z, m[14]); m[15] = fmaf(delta, kd.w, m[15]);
    }

    float* Mr = g_M + ((size_t)b * 128 + r) * 128 + cg * 16;
#pragma unroll
    for (int q4 = 0; q4 < 4; q4++) {
        float4 o; o.x = m[q4*4]; o.y = m[q4*4+1]; o.z = m[q4*4+2]; o.w = m[q4*4+3];
        *(float4*)(Mr + q4 * 4) = o;
    }
}

// ============================================================================
// K4a: read = M @ q (q = raw last-token k); r2 = read @ Wrp + brp
// ============================================================================
__global__ __launch_bounds__(128) void k_read(
    const float* __restrict__ Wrp, const float* __restrict__ brp)
{
    __shared__ __align__(16) float qs[128];
    __shared__ float rs[128];
    const int j = threadIdx.x, b = blockIdx.x;
    const float nq = g_nrm[(size_t)b * L_ + (L_ - 1)];
    qs[j] = g_kn[((size_t)b * L_ + (L_ - 1)) * 128 + j] * nq;
    __syncthreads();
    const float* Mr = g_M + ((size_t)b * 128 + j) * 128;
    float acc = 0.0f;
#pragma unroll 8
    for (int c = 0; c < 128; c += 4) {
        const float4 mm = *(const float4*)(Mr + c);
        const float4 qq = *(const float4*)(qs + c);
        acc = fmaf(mm.x, qq.x, acc); acc = fmaf(mm.y, qq.y, acc);
        acc = fmaf(mm.z, qq.z, acc); acc = fmaf(mm.w, qq.w, acc);
    }
    rs[j] = acc;
    __syncthreads();
    float o = brp[j];
#pragma unroll 8
    for (int h = 0; h < 128; h++) o = fmaf(rs[h], Wrp[h * 128 + j], o);
    g_r2[b * 128 + j] = o;
}

// ============================================================================
// K4b: out[b][v] = r2[b] . Wout[:,v] + bout[v]
// ============================================================================
__global__ __launch_bounds__(256) void k_out(
    const float* __restrict__ Wout, const float* __restrict__ bout,
    float* __restrict__ out)
{
    __shared__ __align__(16) float r2s[128 * 32];   // [h][b]
    const int tid = threadIdx.x;
    const int v = blockIdx.x * 256 + tid;
    for (int e = tid; e < 4096; e += 256) {
        const int bb = e >> 7, h = e & 127;
        r2s[h * 32 + bb] = g_r2[e];
    }
    __syncthreads();
    float acc[32];
#pragma unroll
    for (int bb = 0; bb < 32; bb++) acc[bb] = 0.0f;
#pragma unroll 4
    for (int h = 0; h < 128; h++) {
        const float wv = Wout[(size_t)h * V_ + v];
        const float4* rp = (const float4*)(r2s + h * 32);
#pragma unroll
        for (int q4 = 0; q4 < 8; q4++) {
            const float4 rv = rp[q4];
            acc[q4*4+0] = fmaf(rv.x, wv, acc[q4*4+0]);
            acc[q4*4+1] = fmaf(rv.y, wv, acc[q4*4+1]);
            acc[q4*4+2] = fmaf(rv.z, wv, acc[q4*4+2]);
            acc[q4*4+3] = fmaf(rv.w, wv, acc[q4*4+3]);
        }
    }
    const float bo = bout[v];
#pragma unroll
    for (int bb = 0; bb < 32; bb++)
        out[(size_t)bb * V_ + v] = acc[bb] + bo;
}

// ============================================================================
extern "C" void kernel_launch(void* const* d_in, const int* in_sizes, int n_in,
                              void* d_out, int out_size)
{
    (void)in_sizes; (void)n_in; (void)out_size;
    const int*   seq   = (const int*)  d_in[0];
    const float* embed = (const float*)d_in[1];
    const float* W1    = (const float*)d_in[2];
    const float* b1    = (const float*)d_in[3];
    const float* W2    = (const float*)d_in[4];
    const float* b2    = (const float*)d_in[5];
    const float* ln_g  = (const float*)d_in[6];
    const float* ln_b  = (const float*)d_in[7];
    const float* Wkp   = (const float*)d_in[8];
    const float* Wrp   = (const float*)d_in[9];
    const float* brp   = (const float*)d_in[10];
    const float* Wout  = (const float*)d_in[11];
    const float* bout  = (const float*)d_in[12];
    float* out = (float*)d_out;

    const int smem1 = (32768 + 1024) * 4;           // 135168
    const int smem2 = (52224 + 32) * 4;             // 209024
    cudaFuncSetAttribute(k_ffn1, cudaFuncAttributeMaxDynamicSharedMemorySize, smem1);
    cudaFuncSetAttribute(k_ffn2, cudaFuncAttributeMaxDynamicSharedMemorySize, smem2);

    k_ffn1<<<148, 256, smem1>>>(seq, embed, W1, b1);
    k_ffn2<<<148, 128, smem2>>>(seq, embed, W2, b2, ln_g, ln_b, Wkp);
    k_scan<<<128, 256>>>();
    k_read<<<32, 128>>>(Wrp, brp);
    k_out<<<125, 256>>>(Wout, bout, out);
}

// round 3
// speedup vs baseline: 1.9922x; 1.9922x over previous
#include <cuda_runtime.h>
#include <cuda_bf16.h>
#include <cstdint>

// Problem constants
#define B_ 32
#define L_ 4096
#define H_ 128
#define V_ 32000
#define TOK_ 131072            // B_*L_
#define LN_EPS 1e-5f
#define NORM_EPS 1e-12f

// -------- scratch (device globals; no allocation allowed) --------
__device__ float g_z1[(size_t)V_ * 256];     // relu(h@W1+b1) per vocab   32 MB
__device__ float g_knv[(size_t)V_ * 128];    // normalized k per vocab    16 MB
__device__ float g_nrmv[V_];                 // ||k|| per vocab          128 KB
__device__ float g_kn[(size_t)TOK_ * 128];   // kn per position           64 MB
__device__ float g_nrm[TOK_];                // ||k|| per position       512 KB
__device__ float g_M[(size_t)B_ * 128 * 128];// final scan state           2 MB
__device__ float g_r2[B_ * 128];             // read@Wrp+brp              16 KB

// -------- packed f32x2 helpers --------
__device__ __forceinline__ unsigned long long pk2(float lo, float hi) {
    unsigned long long r;
    asm("mov.b64 %0, {%1, %2};" : "=l"(r) : "f"(lo), "f"(hi));
    return r;
}
__device__ __forceinline__ void upk2(unsigned long long v, float& lo, float& hi) {
    asm("mov.b64 {%0, %1}, %2;" : "=f"(lo), "=f"(hi) : "l"(v));
}
__device__ __forceinline__ unsigned long long fma2(
    unsigned long long a, unsigned long long b, unsigned long long c) {
    unsigned long long d;
    asm("fma.rn.f32x2 %0, %1, %2, %3;" : "=l"(d) : "l"(a), "l"(b), "l"(c));
    return d;
}
__device__ __forceinline__ unsigned long long mul2(
    unsigned long long a, unsigned long long b) {
    unsigned long long d;
    asm("mul.rn.f32x2 %0, %1, %2;" : "=l"(d) : "l"(a), "l"(b));
    return d;
}
__device__ __forceinline__ unsigned long long add2(
    unsigned long long a, unsigned long long b) {
    unsigned long long d;
    asm("add.rn.f32x2 %0, %1, %2;" : "=l"(d) : "l"(a), "l"(b));
    return d;
}

// ============================================================================
// K1: per-VOCAB z1 = relu(embed @ W1 + b1)    (8 vocab rows per pass)
// ============================================================================
__global__ __launch_bounds__(256) void k_ffn1(
    const float* __restrict__ embed,
    const float* __restrict__ W1, const float* __restrict__ b1)
{
    extern __shared__ float sm[];
    float* W1s = sm;            // 128*256
    float* hs  = sm + 32768;    // [i][tok] 128*8
    const int j = threadIdx.x;  // output column 0..255
    for (int i = j; i < 128 * 256; i += 256) W1s[i] = W1[i];
    const float bj = b1[j];
    __syncthreads();

    const int nIter = V_ / 8;
    for (int it = blockIdx.x; it < nIter; it += gridDim.x) {
        const int t0 = it * 8;
        __syncthreads();
        for (int e = j; e < 1024; e += 256) {
            const int tok = e >> 7, i = e & 127;
            hs[i * 8 + tok] = embed[(size_t)(t0 + tok) * 128 + i];
        }
        __syncthreads();
        unsigned long long acc[4];
        const unsigned long long binit = pk2(bj, bj);
#pragma unroll
        for (int q = 0; q < 4; q++) acc[q] = binit;
#pragma unroll 8
        for (int i = 0; i < 128; i++) {
            const float w = W1s[i * 256 + j];
            const unsigned long long wd = pk2(w, w);
            const ulonglong2 A = *(const ulonglong2*)(hs + i * 8);
            const ulonglong2 Bv = *(const ulonglong2*)(hs + i * 8 + 4);
            acc[0] = fma2(A.x, wd, acc[0]);
            acc[1] = fma2(A.y, wd, acc[1]);
            acc[2] = fma2(Bv.x, wd, acc[2]);
            acc[3] = fma2(Bv.y, wd, acc[3]);
        }
#pragma unroll
        for (int q = 0; q < 4; q++) {
            float lo, hi; upk2(acc[q], lo, hi);
            g_z1[(size_t)(t0 + 2 * q)     * 256 + j] = fmaxf(lo, 0.0f);
            g_z1[(size_t)(t0 + 2 * q + 1) * 256 + j] = fmaxf(hi, 0.0f);
        }
    }
}

// ============================================================================
// K2: per-VOCAB y=z1@W2+b2; x=h+y; h2=LN(x); k=h2@Wkp; store kn, ||k||
// 256 threads: j = tid&127 (column), hf = tid>>7 (token sub-block of 8).
// 16 vocab rows per pass.
// ============================================================================
__device__ __forceinline__ void reduceSum8h(float* v, float* red, int tid)
{
#pragma unroll
    for (int k = 0; k < 8; k++) {
        v[k] += __shfl_xor_sync(0xffffffffu, v[k], 16);
        v[k] += __shfl_xor_sync(0xffffffffu, v[k], 8);
        v[k] += __shfl_xor_sync(0xffffffffu, v[k], 4);
        v[k] += __shfl_xor_sync(0xffffffffu, v[k], 2);
        v[k] += __shfl_xor_sync(0xffffffffu, v[k], 1);
    }
    const int w = tid >> 5;          // 0..7 (warps 0-3: hf=0, 4-7: hf=1)
    __syncthreads();
    if ((tid & 31) == 0) {
#pragma unroll
        for (int k = 0; k < 8; k++) red[w * 8 + k] = v[k];
    }
    __syncthreads();
    const int base = (tid >> 7) * 4;  // warps of my half
#pragma unroll
    for (int k = 0; k < 8; k++)
        v[k] = (red[(base + 0) * 8 + k] + red[(base + 1) * 8 + k])
             + (red[(base + 2) * 8 + k] + red[(base + 3) * 8 + k]);
}

__global__ __launch_bounds__(256) void k_ffn2(
    const float* __restrict__ embed,
    const float* __restrict__ W2, const float* __restrict__ b2,
    const float* __restrict__ ln_g, const float* __restrict__ ln_b,
    const float* __restrict__ Wkp)
{
    extern __shared__ float sm[];
    float* W2s  = sm;               // 256*128 floats
    float* Wkps = sm + 32768;       // 128*128
    float* z1s  = sm + 49152;       // [i][tok16] 256*16
    float* h2s  = sm + 53248;       // [i][tok16] 128*16
    float* red  = sm + 55296;       // 8*8
    const int tid = threadIdx.x;
    const int j  = tid & 127;       // column 0..127
    const int hf = tid >> 7;        // token half 0/1
    for (int i = tid; i < 32768; i += 256) W2s[i]  = W2[i];
    for (int i = tid; i < 16384; i += 256) Wkps[i] = Wkp[i];
    const float b2j = b2[j], gj = ln_g[j], bbj = ln_b[j];
    __syncthreads();

    const int nIter = V_ / 16;
    for (int it = blockIdx.x; it < nIter; it += gridDim.x) {
        const int t0 = it * 16;
        const int tl = t0 + hf * 8;
        __syncthreads();
        for (int e = tid; e < 4096; e += 256) {
            const int tok = e >> 8, i = e & 255;
            z1s[i * 16 + tok] = g_z1[(size_t)(t0 + tok) * 256 + i];
        }
        __syncthreads();

        unsigned long long y2[4];
        const unsigned long long binit = pk2(b2j, b2j);
#pragma unroll
        for (int q = 0; q < 4; q++) y2[q] = binit;
#pragma unroll 8
        for (int i = 0; i < 256; i++) {
            const float w = W2s[i * 128 + j];
            const unsigned long long wd = pk2(w, w);
            const ulonglong2 A = *(const ulonglong2*)(z1s + i * 16 + hf * 8);
            const ulonglong2 Bv = *(const ulonglong2*)(z1s + i * 16 + hf * 8 + 4);
            y2[0] = fma2(A.x, wd, y2[0]);
            y2[1] = fma2(A.y, wd, y2[1]);
            y2[2] = fma2(Bv.x, wd, y2[2]);
            y2[3] = fma2(Bv.y, wd, y2[3]);
        }
        float x[8];
#pragma unroll
        for (int q = 0; q < 4; q++) upk2(y2[q], x[2 * q], x[2 * q + 1]);
#pragma unroll
        for (int k = 0; k < 8; k++)
            x[k] += embed[(size_t)(tl + k) * 128 + j];

        float s[8];
#pragma unroll
        for (int k = 0; k < 8; k++) s[k] = x[k];
        reduceSum8h(s, red, tid);
        float vv[8];
#pragma unroll
        for (int k = 0; k < 8; k++) {
            const float d = x[k] - s[k] * (1.0f / 128.0f);
            vv[k] = d * d;
        }
        reduceSum8h(vv, red, tid);
        float h2[8];
#pragma unroll
        for (int k = 0; k < 8; k++) {
            const float mu = s[k] * (1.0f / 128.0f);
            h2[k] = (x[k] - mu) * rsqrtf(vv[k] * (1.0f / 128.0f) + LN_EPS) * gj + bbj;
        }
#pragma unroll
        for (int k = 0; k < 8; k++) h2s[j * 16 + hf * 8 + k] = h2[k];
        __syncthreads();

        unsigned long long kk2[4];
#pragma unroll
        for (int q = 0; q < 4; q++) kk2[q] = 0ull;
#pragma unroll 8
        for (int i = 0; i < 128; i++) {
            const float w = Wkps[i * 128 + j];
            const unsigned long long wd = pk2(w, w);
            const ulonglong2 A = *(const ulonglong2*)(h2s + i * 16 + hf * 8);
            const ulonglong2 Bv = *(const ulonglong2*)(h2s + i * 16 + hf * 8 + 4);
            kk2[0] = fma2(A.x, wd, kk2[0]);
            kk2[1] = fma2(A.y, wd, kk2[1]);
            kk2[2] = fma2(Bv.x, wd, kk2[2]);
            kk2[3] = fma2(Bv.y, wd, kk2[3]);
        }
        float kk[8];
#pragma unroll
        for (int q = 0; q < 4; q++) upk2(kk2[q], kk[2 * q], kk[2 * q + 1]);
        float sq[8];
#pragma unroll
        for (int k = 0; k < 8; k++) sq[k] = kk[k] * kk[k];
        reduceSum8h(sq, red, tid);
#pragma unroll
        for (int k = 0; k < 8; k++) {
            const float nr = fmaxf(sqrtf(sq[k]), NORM_EPS);
            g_knv[(size_t)(tl + k) * 128 + j] = kk[k] / nr;
        }
        if (j < 8) g_nrmv[tl + j] = fmaxf(sqrtf(sq[j]), NORM_EPS);
    }
}

// ============================================================================
// K2b: gather per-position kn / nrm from vocab tables. One warp per token.
// ============================================================================
__global__ __launch_bounds__(256) void k_gather(const int* __restrict__ seq)
{
    const int w = threadIdx.x >> 5, lane = threadIdx.x & 31;
    const int t = blockIdx.x * 8 + w;
    const int v = seq[t];
    const float4* s = (const float4*)(g_knv + (size_t)v * 128);
    float4* d = (float4*)(g_kn + (size_t)t * 128);
    d[lane] = s[lane];
    if (lane == 0) g_nrm[t] = g_nrmv[v];
}

// ============================================================================
// K3: delta-rule scan. 128 CTAs (32 batches x 4 row-splits), per-warp
// cp.async ring (no block barriers). Packed f32x2 FMA + 3x shfl_xor
// butterfly over the 8-lane row group for the dot reduction.
// ============================================================================
#define SCAN_D 8
#define STG_F 164              // floats per stage (656 B)

__global__ __launch_bounds__(256) void k_scan()
{
    __shared__ __align__(16) float buf[8][STG_F * SCAN_D];
    const int tid  = threadIdx.x;
    const int w    = tid >> 5, lane = tid & 31;
    const int cg   = lane & 7, rr = lane >> 3;
    const int b    = blockIdx.x >> 2, s = blockIdx.x & 3;
    const int r    = s * 32 + w * 4 + rr;           // global row 0..127
    const float* __restrict__ knb  = g_kn + (size_t)b * L_ * 128;
    const float* __restrict__ nrmb = g_nrm + (size_t)b * L_;
    float* wb = &buf[w][0];
    const uint32_t wbb = (uint32_t)__cvta_generic_to_shared(wb);
    const int NSTEP = L_ - 1;

    // prologue: stages 0..6
    for (int t = 0; t < SCAN_D - 1; t++) {
        const uint32_t dst = wbb + t * 656 + (lane >> 2) * 80 + (lane & 3) * 16;
        const float* src = knb + (size_t)t * 128 + lane * 4;
        asm volatile("cp.async.cg.shared.global [%0], [%1], 16;\n" :: "r"(dst), "l"(src) : "memory");
        if (lane == 0) {
            const uint32_t dn = wbb + t * 656 + 640;
            asm volatile("cp.async.ca.shared.global [%0], [%1], 4;\n" :: "r"(dn), "l"(nrmb + t) : "memory");
        }
        asm volatile("cp.async.commit_group;\n" ::: "memory");
    }

    unsigned long long m2[8];
#pragma unroll
    for (int c = 0; c < 8; c++) m2[c] = 0ull;
    const int kroff = (r >> 4) * 20 + (r & 15);     // kn[r] float offset in stage

    for (int t = 0; t < NSTEP; t++) {
        asm volatile("cp.async.wait_group 6;\n" ::: "memory");
        __syncwarp();
        {   // refill
            const int ti = t + SCAN_D - 1;
            if (ti < NSTEP) {
                const int slot = ti & 7;
                const uint32_t dst = wbb + slot * 656 + (lane >> 2) * 80 + (lane & 3) * 16;
                const float* src = knb + (size_t)ti * 128 + lane * 4;
                asm volatile("cp.async.cg.shared.global [%0], [%1], 16;\n" :: "r"(dst), "l"(src) : "memory");
                if (lane == 0) {
                    const uint32_t dn = wbb + slot * 656 + 640;
                    asm volatile("cp.async.ca.shared.global [%0], [%1], 4;\n" :: "r"(dn), "l"(nrmb + ti) : "memory");
                }
            }
            asm volatile("cp.async.commit_group;\n" ::: "memory");
        }
        const float* st = wb + (t & 7) * STG_F;
        const ulonglong2 kA = *(const ulonglong2*)(st + cg * 20);
        const ulonglong2 kB = *(const ulonglong2*)(st + cg * 20 + 4);
        const ulonglong2 kC = *(const ulonglong2*)(st + cg * 20 + 8);
        const ulonglong2 kD = *(const ulonglong2*)(st + cg * 20 + 12);
        const float nrm = st[160];
        const float kr  = st[kroff] * nrm;          // raw k[r]

        unsigned long long a0 = mul2(m2[0], kA.x); a0 = fma2(m2[4], kC.x, a0);
        unsigned long long a1 = mul2(m2[1], kA.y); a1 = fma2(m2[5], kC.y, a1);
        unsigned long long a2 = mul2(m2[2], kB.x); a2 = fma2(m2[6], kD.x, a2);
        unsigned long long a3 = mul2(m2[3], kB.y); a3 = fma2(m2[7], kD.y, a3);
        const unsigned long long sAll = add2(add2(a0, a1), add2(a2, a3));
        float plo, phi; upk2(sAll, plo, phi);
        float dot = plo + phi;
        dot += __shfl_xor_sync(0xffffffffu, dot, 1);
        dot += __shfl_xor_sync(0xffffffffu, dot, 2);
        dot += __shfl_xor_sync(0xffffffffu, dot, 4);
        const float delta = kr - dot;
        const unsigned long long d2 = pk2(delta, delta);
        m2[0] = fma2(d2, kA.x, m2[0]);
        m2[1] = fma2(d2, kA.y, m2[1]);
        m2[2] = fma2(d2, kB.x, m2[2]);
        m2[3] = fma2(d2, kB.y, m2[3]);
        m2[4] = fma2(d2, kC.x, m2[4]);
        m2[5] = fma2(d2, kC.y, m2[5]);
        m2[6] = fma2(d2, kD.x, m2[6]);
        m2[7] = fma2(d2, kD.y, m2[7]);
    }

    float* Mr = g_M + ((size_t)b * 128 + r) * 128 + cg * 16;
#pragma unroll
    for (int c = 0; c < 8; c += 2) {
        float x0, x1, x2, x3;
        upk2(m2[c], x0, x1); upk2(m2[c + 1], x2, x3);
        float4 o; o.x = x0; o.y = x1; o.z = x2; o.w = x3;
        *(float4*)(Mr + c * 2) = o;
    }
}

// ============================================================================
// K4a: read = M @ q (q = raw last-token k); r2 = read @ Wrp + brp
// ============================================================================
__global__ __launch_bounds__(128) void k_read(
    const float* __restrict__ Wrp, const float* __restrict__ brp)
{
    __shared__ __align__(16) float qs[128];
    __shared__ float rs[128];
    const int j = threadIdx.x, b = blockIdx.x;
    const float nq = g_nrm[(size_t)b * L_ + (L_ - 1)];
    qs[j] = g_kn[((size_t)b * L_ + (L_ - 1)) * 128 + j] * nq;
    __syncthreads();
    const float* Mr = g_M + ((size_t)b * 128 + j) * 128;
    float acc = 0.0f;
#pragma unroll 8
    for (int c = 0; c < 128; c += 4) {
        const float4 mm = *(const float4*)(Mr + c);
        const float4 qq = *(const float4*)(qs + c);
        acc = fmaf(mm.x, qq.x, acc); acc = fmaf(mm.y, qq.y, acc);
        acc = fmaf(mm.z, qq.z, acc); acc = fmaf(mm.w, qq.w, acc);
    }
    rs[j] = acc;
    __syncthreads();
    float o = brp[j];
#pragma unroll 8
    for (int h = 0; h < 128; h++) o = fmaf(rs[h], Wrp[h * 128 + j], o);
    g_r2[b * 128 + j] = o;
}

// ============================================================================
// K4b: out[b][v] = r2[b] . Wout[:,v] + bout[v]
// ============================================================================
__global__ __launch_bounds__(256) void k_out(
    const float* __restrict__ Wout, const float* __restrict__ bout,
    float* __restrict__ out)
{
    __shared__ __align__(16) float r2s[128 * 32];   // [h][b]
    const int tid = threadIdx.x;
    const int v = blockIdx.x * 256 + tid;
    for (int e = tid; e < 4096; e += 256) {
        const int bb = e >> 7, h = e & 127;
        r2s[h * 32 + bb] = g_r2[e];
    }
    __syncthreads();
    float acc[32];
#pragma unroll
    for (int bb = 0; bb < 32; bb++) acc[bb] = 0.0f;
#pragma unroll 4
    for (int h = 0; h < 128; h++) {
        const float wv = Wout[(size_t)h * V_ + v];
        const float4* rp = (const float4*)(r2s + h * 32);
#pragma unroll
        for (int q4 = 0; q4 < 8; q4++) {
            const float4 rv = rp[q4];
            acc[q4*4+0] = fmaf(rv.x, wv, acc[q4*4+0]);
            acc[q4*4+1] = fmaf(rv.y, wv, acc[q4*4+1]);
            acc[q4*4+2] = fmaf(rv.z, wv, acc[q4*4+2]);
            acc[q4*4+3] = fmaf(rv.w, wv, acc[q4*4+3]);
        }
    }
    const float bo = bout[v];
#pragma unroll
    for (int bb = 0; bb < 32; bb++)
        out[(size_t)bb * V_ + v] = acc[bb] + bo;
}

// ============================================================================
extern "C" void kernel_launch(void* const* d_in, const int* in_sizes, int n_in,
                              void* d_out, int out_size)
{
    (void)in_sizes; (void)n_in; (void)out_size;
    const int*   seq   = (const int*)  d_in[0];
    const float* embed = (const float*)d_in[1];
    const float* W1    = (const float*)d_in[2];
    const float* b1    = (const float*)d_in[3];
    const float* W2    = (const float*)d_in[4];
    const float* b2    = (const float*)d_in[5];
    const float* ln_g  = (const float*)d_in[6];
    const float* ln_b  = (const float*)d_in[7];
    const float* Wkp   = (const float*)d_in[8];
    const float* Wrp   = (const float*)d_in[9];
    const float* brp   = (const float*)d_in[10];
    const float* Wout  = (const float*)d_in[11];
    const float* bout  = (const float*)d_in[12];
    float* out = (float*)d_out;

    const int smem1 = (32768 + 1024) * 4;            // 135168
    const int smem2 = (55296 + 64) * 4;              // 221440
    cudaFuncSetAttribute(k_ffn1, cudaFuncAttributeMaxDynamicSharedMemorySize, smem1);
    cudaFuncSetAttribute(k_ffn2, cudaFuncAttributeMaxDynamicSharedMemorySize, smem2);

    k_ffn1<<<148, 256, smem1>>>(embed, W1, b1);
    k_ffn2<<<148, 256, smem2>>>(embed, W2, b2, ln_g, ln_b, Wkp);
    k_gather<<<TOK_ / 8, 256>>>(seq);
    k_scan<<<128, 256>>>();
    k_read<<<32, 128>>>(Wrp, brp);
    k_out<<<125, 256>>>(Wout, bout, out);
}